// round 4
// baseline (speedup 1.0000x reference)
#include <cuda_runtime.h>

#define E_DIM 128
#define TT 64
#define NTHREADS 256

__global__ void __launch_bounds__(NTHREADS, 1)
attn_mv_kernel(const float* __restrict__ gm, const float* __restrict__ gv,
               const float* __restrict__ gW, const float* __restrict__ gb,
               float* __restrict__ gout, int T)
{
    extern __shared__ float smem[];
    float* sW = smem;                         // 128*128 floats (64 KB), reused as P later
    float* sM = sW + E_DIM * E_DIM;           // TT*128 (32 KB)
    float* sU = sM + TT * E_DIM;              // TT*128 (32 KB)
    float* sV = sU + TT * E_DIM;              // TT*128 (32 KB)
    __shared__ float sSum[E_DIM];             // colsum of m_b
    __shared__ float sWgt[E_DIM];             // s[e] / rowsum[e]

    const int b   = blockIdx.x;
    const int tid = threadIdx.x;

    const float* Wb = gW + (size_t)b * E_DIM * E_DIM;
    const float* mb = gm + (size_t)b * T * E_DIM;

    // ---- stage W_b into smem ----
    {
        const float4* W4  = (const float4*)Wb;
        float4*       sW4 = (float4*)sW;
        #pragma unroll
        for (int i = tid; i < E_DIM * E_DIM / 4; i += NTHREADS) sW4[i] = W4[i];
    }
    if (tid < E_DIM) sSum[tid] = 0.0f;

    // P accumulator: each thread owns an 8x8 block of the 128x128 P matrix
    float P[8][8];
    #pragma unroll
    for (int i = 0; i < 8; i++)
        #pragma unroll
        for (int j = 0; j < 8; j++) P[i][j] = 0.0f;

    const int fg = tid & 15;       // 16 f-groups
    const int tg = tid >> 4;       // 16 t/e-groups
    const int f0 = fg * 8;         // f block (both GEMMs)
    const int t0 = tg * 4;         // GEMM1: 4 time rows
    const int e0 = tg * 8;         // GEMM2: 8 e rows

    const int col = (tid * 4) & (E_DIM - 1);  // fixed column set this thread loads

    __syncthreads();  // sSum zero + sW visible

    const int ntiles = T / TT;
    for (int tile = 0; tile < ntiles; ++tile) {
        // ---- load m tile + v tile, fold in colsum partials ----
        {
            const float4* m4 = (const float4*)(mb + (size_t)tile * TT * E_DIM);
            const float4* v4 = (const float4*)(gv + (size_t)tile * TT * E_DIM);
            float4* sM4 = (float4*)sM;
            float4* sV4 = (float4*)sV;
            float c0 = 0.f, c1 = 0.f, c2 = 0.f, c3 = 0.f;
            #pragma unroll
            for (int k = 0; k < (TT * E_DIM / 4) / NTHREADS; ++k) {
                int i = tid + k * NTHREADS;
                float4 a = m4[i];
                sM4[i] = a;
                sV4[i] = v4[i];
                c0 += a.x; c1 += a.y; c2 += a.z; c3 += a.w;
            }
            atomicAdd(&sSum[col + 0], c0);
            atomicAdd(&sSum[col + 1], c1);
            atomicAdd(&sSum[col + 2], c2);
            atomicAdd(&sSum[col + 3], c3);
        }
        __syncthreads();

        // ---- GEMM1: acc(4x8) = m(t0..t0+3, :) @ W(:, f0..f0+7) ----
        float acc[4][8];
        #pragma unroll
        for (int i = 0; i < 4; i++)
            #pragma unroll
            for (int j = 0; j < 8; j++) acc[i][j] = 0.0f;

        #pragma unroll 4
        for (int e = 0; e < E_DIM; ++e) {
            const float4 wa = *(const float4*)(sW + e * E_DIM + f0);
            const float4 wc = *(const float4*)(sW + e * E_DIM + f0 + 4);
            const float wr[8] = {wa.x, wa.y, wa.z, wa.w, wc.x, wc.y, wc.z, wc.w};
            float mr[4];
            #pragma unroll
            for (int i = 0; i < 4; i++) mr[i] = sM[(t0 + i) * E_DIM + e];
            #pragma unroll
            for (int i = 0; i < 4; i++)
                #pragma unroll
                for (int j = 0; j < 8; j++)
                    acc[i][j] = fmaf(mr[i], wr[j], acc[i][j]);
        }

        // ---- bias + tanh -> sU ----
        {
            const float* brow = gb + (size_t)(tile * TT + t0) * E_DIM + f0;
            #pragma unroll
            for (int i = 0; i < 4; i++) {
                float4 b0 = *(const float4*)(brow + i * E_DIM);
                float4 b1 = *(const float4*)(brow + i * E_DIM + 4);
                const float bz[8] = {b0.x, b0.y, b0.z, b0.w, b1.x, b1.y, b1.z, b1.w};
                float uo[8];
                #pragma unroll
                for (int j = 0; j < 8; j++) {
                    float x  = acc[i][j] + bz[j];
                    float ex = __expf(2.0f * x);           // tanh(x) = 1 - 2/(e^{2x}+1)
                    uo[j] = 1.0f - __fdividef(2.0f, ex + 1.0f);
                }
                *(float4*)(sU + (t0 + i) * E_DIM + f0)     = make_float4(uo[0], uo[1], uo[2], uo[3]);
                *(float4*)(sU + (t0 + i) * E_DIM + f0 + 4) = make_float4(uo[4], uo[5], uo[6], uo[7]);
            }
        }
        __syncthreads();

        // ---- GEMM2: P(e0..e0+7, f0..f0+7) += v^T u over this tile ----
        #pragma unroll 2
        for (int t = 0; t < TT; ++t) {
            const float4 va = *(const float4*)(sV + t * E_DIM + e0);
            const float4 vc = *(const float4*)(sV + t * E_DIM + e0 + 4);
            const float4 ua = *(const float4*)(sU + t * E_DIM + f0);
            const float4 uc = *(const float4*)(sU + t * E_DIM + f0 + 4);
            const float vr[8] = {va.x, va.y, va.z, va.w, vc.x, vc.y, vc.z, vc.w};
            const float ur[8] = {ua.x, ua.y, ua.z, ua.w, uc.x, uc.y, uc.z, uc.w};
            #pragma unroll
            for (int i = 0; i < 8; i++)
                #pragma unroll
                for (int j = 0; j < 8; j++)
                    P[i][j] = fmaf(vr[i], ur[j], P[i][j]);
        }
        __syncthreads();   // protect sM/sV/sU before next tile overwrite
    }

    // ---- epilogue: P -> smem (reuse sW), softmax rows, GEMV with colsums ----
    float* sP = sW;
    #pragma unroll
    for (int i = 0; i < 8; i++) {
        *(float4*)(sP + (e0 + i) * E_DIM + f0)     = make_float4(P[i][0], P[i][1], P[i][2], P[i][3]);
        *(float4*)(sP + (e0 + i) * E_DIM + f0 + 4) = make_float4(P[i][4], P[i][5], P[i][6], P[i][7]);
    }
    __syncthreads();

    const int warp = tid >> 5;
    const int lane = tid & 31;
    for (int e = warp; e < E_DIM; e += 8) {
        float x0 = sP[e * E_DIM + lane];
        float x1 = sP[e * E_DIM + lane + 32];
        float x2 = sP[e * E_DIM + lane + 64];
        float x3 = sP[e * E_DIM + lane + 96];
        float mx = fmaxf(fmaxf(x0, x1), fmaxf(x2, x3));
        #pragma unroll
        for (int o = 16; o > 0; o >>= 1) mx = fmaxf(mx, __shfl_xor_sync(0xffffffffu, mx, o));
        float g0 = __expf(x0 - mx);
        float g1 = __expf(x1 - mx);
        float g2 = __expf(x2 - mx);
        float g3 = __expf(x3 - mx);
        float sm = g0 + g1 + g2 + g3;
        #pragma unroll
        for (int o = 16; o > 0; o >>= 1) sm += __shfl_xor_sync(0xffffffffu, sm, o);
        sP[e * E_DIM + lane]      = g0;
        sP[e * E_DIM + lane + 32] = g1;
        sP[e * E_DIM + lane + 64] = g2;
        sP[e * E_DIM + lane + 96] = g3;
        if (lane == 0) sWgt[e] = sSum[e] / sm;   // fold colsum and 1/rowsum together
    }
    __syncthreads();

    if (tid < E_DIM) {
        float o = 0.0f;
        #pragma unroll 8
        for (int e = 0; e < E_DIM; ++e)
            o = fmaf(sWgt[e], sP[e * E_DIM + tid], o);
        gout[(size_t)b * E_DIM + tid] = o;
    }
}

extern "C" void kernel_launch(void* const* d_in, const int* in_sizes, int n_in,
                              void* d_out, int out_size)
{
    const float* m  = (const float*)d_in[0];   // (B, T, E)
    const float* v  = (const float*)d_in[1];   // (B, E)   (indexed by time, T==B)
    const float* W  = (const float*)d_in[2];   // (B, E, E)
    const float* bb = (const float*)d_in[3];   // (B, E)   bias, indexed by time
    float* out = (float*)d_out;                // (B, E)

    const int BE = in_sizes[1];        // B * E
    const int Bn = BE / E_DIM;         // 1024
    const int T  = in_sizes[0] / BE;   // 1024

    const size_t smem_bytes = (size_t)(E_DIM * E_DIM + 3 * TT * E_DIM) * sizeof(float); // 160 KB
    cudaFuncSetAttribute(attn_mv_kernel, cudaFuncAttributeMaxDynamicSharedMemorySize,
                         (int)smem_bytes);
    attn_mv_kernel<<<Bn, NTHREADS, smem_bytes>>>(m, v, W, bb, out, T);
}

// round 5
// speedup vs baseline: 1.0122x; 1.0122x over previous
#include <cuda_runtime.h>

#define E_DIM 128
#define TT 64
#define NTHREADS 256

typedef unsigned long long u64;

__device__ __forceinline__ u64 pack2(float lo, float hi) {
    u64 r; asm("mov.b64 %0, {%1, %2};" : "=l"(r) : "f"(lo), "f"(hi)); return r;
}
__device__ __forceinline__ u64 bcast2(float x) { return pack2(x, x); }
__device__ __forceinline__ void unpack2(u64 p, float& lo, float& hi) {
    asm("mov.b64 {%0, %1}, %2;" : "=f"(lo), "=f"(hi) : "l"(p));
}
__device__ __forceinline__ void fma2(u64& d, u64 a, u64 b) {
    asm("fma.rn.f32x2 %0, %1, %2, %0;" : "+l"(d) : "l"(a), "l"(b));
}

__global__ void __launch_bounds__(NTHREADS, 1)
attn_mv_kernel(const float* __restrict__ gm, const float* __restrict__ gv,
               const float* __restrict__ gW, const float* __restrict__ gb,
               float* __restrict__ gout, int T)
{
    extern __shared__ float smem[];
    float* sW = smem;                         // 128*128 floats (64 KB), reused as P later
    float* sM = sW + E_DIM * E_DIM;           // TT*128 (32 KB)
    float* sU = sM + TT * E_DIM;              // TT*128 (32 KB)
    float* sV = sU + TT * E_DIM;              // TT*128 (32 KB)
    __shared__ float sSum[E_DIM];             // colsum of m_b
    __shared__ float sWgt[E_DIM];             // s[e] / rowsum[e]

    const int b   = blockIdx.x;
    const int tid = threadIdx.x;

    const float* Wb = gW + (size_t)b * E_DIM * E_DIM;
    const float* mb = gm + (size_t)b * T * E_DIM;

    // ---- stage W_b into smem ----
    {
        const float4* W4  = (const float4*)Wb;
        float4*       sW4 = (float4*)sW;
        #pragma unroll
        for (int i = tid; i < E_DIM * E_DIM / 4; i += NTHREADS) sW4[i] = W4[i];
    }
    if (tid < E_DIM) sSum[tid] = 0.0f;

    // P accumulator: 8 e-rows x 8 f-cols per thread, packed as 8x4 f32x2
    u64 P2[8][4];
    #pragma unroll
    for (int i = 0; i < 8; i++)
        #pragma unroll
        for (int j = 0; j < 4; j++) P2[i][j] = 0ull;

    const int fg = tid & 15;       // 16 f-groups
    const int tg = tid >> 4;       // 16 t/e-groups
    const int f0 = fg * 8;         // f block (both GEMMs)
    const int t0 = tg * 4;         // GEMM1: 4 time rows
    const int e0 = tg * 8;         // GEMM2: 8 e rows

    const int col = (tid * 4) & (E_DIM - 1);  // fixed column set this thread loads

    __syncthreads();  // sSum zero + sW visible

    const int ntiles = T / TT;
    for (int tile = 0; tile < ntiles; ++tile) {
        // ---- load m tile + v tile, fold in colsum partials ----
        {
            const float4* m4 = (const float4*)(mb + (size_t)tile * TT * E_DIM);
            const float4* v4 = (const float4*)(gv + (size_t)tile * TT * E_DIM);
            float4* sM4 = (float4*)sM;
            float4* sV4 = (float4*)sV;
            float c0 = 0.f, c1 = 0.f, c2 = 0.f, c3 = 0.f;
            #pragma unroll
            for (int k = 0; k < (TT * E_DIM / 4) / NTHREADS; ++k) {
                int i = tid + k * NTHREADS;
                float4 a = m4[i];
                sM4[i] = a;
                sV4[i] = v4[i];
                c0 += a.x; c1 += a.y; c2 += a.z; c3 += a.w;
            }
            atomicAdd(&sSum[col + 0], c0);
            atomicAdd(&sSum[col + 1], c1);
            atomicAdd(&sSum[col + 2], c2);
            atomicAdd(&sSum[col + 3], c3);
        }
        __syncthreads();

        // ---- GEMM1 (packed f32x2): acc(4 rows x 4 pairs) = m @ W ----
        u64 acc2[4][4];
        #pragma unroll
        for (int i = 0; i < 4; i++)
            #pragma unroll
            for (int j = 0; j < 4; j++) acc2[i][j] = 0ull;

        #pragma unroll 4
        for (int e = 0; e < E_DIM; ++e) {
            const ulonglong2* wrow = (const ulonglong2*)(sW + e * E_DIM + f0);
            const ulonglong2 wa = wrow[0];
            const ulonglong2 wb2 = wrow[1];
            const u64 w2[4] = {wa.x, wa.y, wb2.x, wb2.y};
            u64 mb2[4];
            #pragma unroll
            for (int i = 0; i < 4; i++) mb2[i] = bcast2(sM[(t0 + i) * E_DIM + e]);
            #pragma unroll
            for (int i = 0; i < 4; i++)
                #pragma unroll
                for (int j = 0; j < 4; j++)
                    fma2(acc2[i][j], mb2[i], w2[j]);
        }

        // ---- bias + tanh -> sU ----
        {
            const float* brow = gb + (size_t)(tile * TT + t0) * E_DIM + f0;
            #pragma unroll
            for (int i = 0; i < 4; i++) {
                float4 b0 = *(const float4*)(brow + i * E_DIM);
                float4 b1 = *(const float4*)(brow + i * E_DIM + 4);
                const float bz[8] = {b0.x, b0.y, b0.z, b0.w, b1.x, b1.y, b1.z, b1.w};
                float av[8];
                #pragma unroll
                for (int j = 0; j < 4; j++) unpack2(acc2[i][j], av[2 * j], av[2 * j + 1]);
                float uo[8];
                #pragma unroll
                for (int j = 0; j < 8; j++) {
                    float x  = av[j] + bz[j];
                    float ex = __expf(2.0f * x);           // tanh(x) = 1 - 2/(e^{2x}+1)
                    uo[j] = 1.0f - __fdividef(2.0f, ex + 1.0f);
                }
                *(float4*)(sU + (t0 + i) * E_DIM + f0)     = make_float4(uo[0], uo[1], uo[2], uo[3]);
                *(float4*)(sU + (t0 + i) * E_DIM + f0 + 4) = make_float4(uo[4], uo[5], uo[6], uo[7]);
            }
        }
        __syncthreads();

        // ---- GEMM2 (packed f32x2): P(8 e-rows x 4 f-pairs) += v^T u ----
        #pragma unroll 2
        for (int t = 0; t < TT; ++t) {
            const ulonglong2* up = (const ulonglong2*)(sU + t * E_DIM + f0);
            const ulonglong2 ua = up[0];
            const ulonglong2 ub = up[1];
            const u64 u2[4] = {ua.x, ua.y, ub.x, ub.y};
            const float4 va = *(const float4*)(sV + t * E_DIM + e0);
            const float4 vc = *(const float4*)(sV + t * E_DIM + e0 + 4);
            const float vs[8] = {va.x, va.y, va.z, va.w, vc.x, vc.y, vc.z, vc.w};
            u64 vb2[8];
            #pragma unroll
            for (int i = 0; i < 8; i++) vb2[i] = bcast2(vs[i]);
            #pragma unroll
            for (int i = 0; i < 8; i++)
                #pragma unroll
                for (int j = 0; j < 4; j++)
                    fma2(P2[i][j], vb2[i], u2[j]);
        }
        __syncthreads();   // protect sM/sV/sU before next tile overwrite
    }

    // ---- epilogue: P -> smem (reuse sW), softmax rows, GEMV with colsums ----
    float* sP = sW;
    #pragma unroll
    for (int i = 0; i < 8; i++) {
        ulonglong2* rowp = (ulonglong2*)(sP + (e0 + i) * E_DIM + f0);
        ulonglong2 r0, r1;
        r0.x = P2[i][0]; r0.y = P2[i][1];
        r1.x = P2[i][2]; r1.y = P2[i][3];
        rowp[0] = r0;
        rowp[1] = r1;
    }
    __syncthreads();

    const int warp = tid >> 5;
    const int lane = tid & 31;
    for (int e = warp; e < E_DIM; e += 8) {
        float x0 = sP[e * E_DIM + lane];
        float x1 = sP[e * E_DIM + lane + 32];
        float x2 = sP[e * E_DIM + lane + 64];
        float x3 = sP[e * E_DIM + lane + 96];
        float mx = fmaxf(fmaxf(x0, x1), fmaxf(x2, x3));
        #pragma unroll
        for (int o = 16; o > 0; o >>= 1) mx = fmaxf(mx, __shfl_xor_sync(0xffffffffu, mx, o));
        float g0 = __expf(x0 - mx);
        float g1 = __expf(x1 - mx);
        float g2 = __expf(x2 - mx);
        float g3 = __expf(x3 - mx);
        float sm = g0 + g1 + g2 + g3;
        #pragma unroll
        for (int o = 16; o > 0; o >>= 1) sm += __shfl_xor_sync(0xffffffffu, sm, o);
        sP[e * E_DIM + lane]      = g0;
        sP[e * E_DIM + lane + 32] = g1;
        sP[e * E_DIM + lane + 64] = g2;
        sP[e * E_DIM + lane + 96] = g3;
        if (lane == 0) sWgt[e] = sSum[e] / sm;   // fold colsum and 1/rowsum together
    }
    __syncthreads();

    if (tid < E_DIM) {
        float o = 0.0f;
        #pragma unroll 8
        for (int e = 0; e < E_DIM; ++e)
            o = fmaf(sWgt[e], sP[e * E_DIM + tid], o);
        gout[(size_t)b * E_DIM + tid] = o;
    }
}

extern "C" void kernel_launch(void* const* d_in, const int* in_sizes, int n_in,
                              void* d_out, int out_size)
{
    const float* m  = (const float*)d_in[0];   // (B, T, E)
    const float* v  = (const float*)d_in[1];   // (B, E)   (indexed by time, T==B)
    const float* W  = (const float*)d_in[2];   // (B, E, E)
    const float* bb = (const float*)d_in[3];   // (B, E)   bias, indexed by time
    float* out = (float*)d_out;                // (B, E)

    const int BE = in_sizes[1];        // B * E
    const int Bn = BE / E_DIM;         // 1024
    const int T  = in_sizes[0] / BE;   // 1024

    const size_t smem_bytes = (size_t)(E_DIM * E_DIM + 3 * TT * E_DIM) * sizeof(float); // 160 KB
    cudaFuncSetAttribute(attn_mv_kernel, cudaFuncAttributeMaxDynamicSharedMemorySize,
                         (int)smem_bytes);
    attn_mv_kernel<<<Bn, NTHREADS, smem_bytes>>>(m, v, W, bb, out, T);
}

// round 9
// speedup vs baseline: 1.9103x; 1.8873x over previous
#include <cuda_runtime.h>
#include <cuda_bf16.h>
#include <stdint.h>

#define E_DIM 128
#define TT 64
#define NTHREADS 256
#define NTILES 16
// smem strides in bf16 elements (odd multiples of 8 -> 16B-aligned rows, conflict-free ldmatrix)
#define SW_STR 136
#define SM_STR 136
#define SU_STR 136
#define SV_STR 72

// byte offsets from 1024-aligned smem base
#define OFF_WH 0u
#define OFF_WL 34816u
#define OFF_MH 69632u
#define OFF_ML 87040u
#define OFF_VH 104448u
#define OFF_VL 122880u
#define OFF_UH 141312u
#define OFF_UL 158720u
#define OFF_B  176128u
#define OFF_SUM 208896u
#define SMEM_REQ (209408 + 1024)

// v^T split, shared by all batches: [E rows][1024 t cols]
__device__ __nv_bfloat16 g_vT_hi[E_DIM * 1024];
__device__ __nv_bfloat16 g_vT_lo[E_DIM * 1024];

__device__ __forceinline__ uint32_t s2u(const void* p) {
    uint32_t a;
    asm("{ .reg .u64 t; cvta.to.shared.u64 t, %1; cvt.u32.u64 %0, t; }" : "=r"(a) : "l"(p));
    return a;
}
__device__ __forceinline__ void ldsm_x4(uint32_t* r, uint32_t a) {
    asm volatile("ldmatrix.sync.aligned.m8n8.x4.shared.b16 {%0,%1,%2,%3}, [%4];"
                 : "=r"(r[0]), "=r"(r[1]), "=r"(r[2]), "=r"(r[3]) : "r"(a));
}
__device__ __forceinline__ void ldsm_x4t(uint32_t* r, uint32_t a) {
    asm volatile("ldmatrix.sync.aligned.m8n8.x4.trans.shared.b16 {%0,%1,%2,%3}, [%4];"
                 : "=r"(r[0]), "=r"(r[1]), "=r"(r[2]), "=r"(r[3]) : "r"(a));
}
__device__ __forceinline__ void mma16816(float* c, const uint32_t* a, const uint32_t* b) {
    asm volatile("mma.sync.aligned.m16n8k16.row.col.f32.bf16.bf16.f32 "
                 "{%0,%1,%2,%3}, {%4,%5,%6,%7}, {%8,%9}, {%0,%1,%2,%3};"
                 : "+f"(c[0]), "+f"(c[1]), "+f"(c[2]), "+f"(c[3])
                 : "r"(a[0]), "r"(a[1]), "r"(a[2]), "r"(a[3]), "r"(b[0]), "r"(b[1]));
}
__device__ __forceinline__ uint32_t pkbf2(__nv_bfloat16 a, __nv_bfloat16 b) {
    __nv_bfloat162 t = __halves2bfloat162(a, b);
    return *(uint32_t*)&t;
}
__device__ __forceinline__ void split2(float x0, float x1, uint32_t& hi, uint32_t& lo) {
    __nv_bfloat16 h0 = __float2bfloat16(x0);
    __nv_bfloat16 h1 = __float2bfloat16(x1);
    hi = pkbf2(h0, h1);
    lo = pkbf2(__float2bfloat16(x0 - __bfloat162float(h0)),
               __float2bfloat16(x1 - __bfloat162float(h1)));
}
__device__ __forceinline__ float tanh_fast(float x) {
    float ex = __expf(2.0f * x);
    return 1.0f - __fdividef(2.0f, ex + 1.0f);
}

// ---------------- precompute: split v^T ----------------
__global__ void vsplit_kernel(const float* __restrict__ gv) {
    int w = blockIdx.x * blockDim.x + threadIdx.x;   // 0 .. 131071
    int e = w >> 10, t = w & 1023;
    float x = gv[t * E_DIM + e];
    __nv_bfloat16 h = __float2bfloat16(x);
    g_vT_hi[w] = h;
    g_vT_lo[w] = __float2bfloat16(x - __bfloat162float(h));
}

// ---------------- main kernel ----------------
__global__ void __launch_bounds__(NTHREADS, 1)
attn_mv_mma(const float* __restrict__ gm, const float* __restrict__ gW,
            const float* __restrict__ gb, float* __restrict__ gout)
{
    extern __shared__ char raw[];
    char* base = (char*)(((uintptr_t)raw + 1023) & ~(uintptr_t)1023);
    const uint32_t sb = s2u(base);
    float* sB   = (float*)(base + OFF_B);
    float* sSum = (float*)(base + OFF_SUM);

    const int b    = blockIdx.x;
    const int tid  = threadIdx.x;
    const int lane = tid & 31;
    const int wid  = tid >> 5;

    const float* mb = gm + (size_t)b * 1024 * E_DIM;

    // ---- stage W split into smem [e rows][f cols], hi/lo ----
    {
        const float4* W4 = (const float4*)(gW + (size_t)b * E_DIM * E_DIM);
        for (int i = tid; i < E_DIM * 32; i += NTHREADS) {
            int e  = i >> 5;
            int f4 = (i & 31) * 4;
            float4 w = W4[i];
            uint32_t h0, l0, h1, l1;
            split2(w.x, w.y, h0, l0);
            split2(w.z, w.w, h1, l1);
            uint32_t off = (uint32_t)(e * SW_STR + f4) * 2u;
            *(uint2*)(base + OFF_WH + off) = make_uint2(h0, h1);
            *(uint2*)(base + OFF_WL + off) = make_uint2(l0, l1);
        }
    }
    if (tid < E_DIM) sSum[tid] = 0.0f;

    // P accumulators: warp wid owns e-rows [wid*16, wid*16+16), all 128 f cols
    float P[16][4];
    #pragma unroll
    for (int q = 0; q < 16; ++q)
        #pragma unroll
        for (int j = 0; j < 4; ++j) P[q][j] = 0.0f;

    __syncthreads();

    // lane-invariant ldmatrix address pieces
    const int lrow = (lane & 7) + ((lane >> 3) & 1) * 8;   // row within 16-row block
    const int lcol = (lane >> 4) * 8;                      // 8-col group select
    const int e4c  = (tid & 31) * 4;                       // colsum column set

    for (int tile = 0; tile < NTILES; ++tile) {
        // ---- load+split m tile [64 x 128], fold colsum ----
        {
            const float4* m4 = (const float4*)(mb + (size_t)tile * TT * E_DIM);
            float c0 = 0.f, c1 = 0.f, c2 = 0.f, c3 = 0.f;
            #pragma unroll
            for (int k = 0; k < (TT * E_DIM / 4) / NTHREADS; ++k) {   // 8 iters
                int i  = tid + k * NTHREADS;
                int t  = i >> 5;
                int e4 = (i & 31) * 4;
                float4 a = m4[i];
                uint32_t h0, l0, h1, l1;
                split2(a.x, a.y, h0, l0);
                split2(a.z, a.w, h1, l1);
                uint32_t off = (uint32_t)(t * SM_STR + e4) * 2u;
                *(uint2*)(base + OFF_MH + off) = make_uint2(h0, h1);
                *(uint2*)(base + OFF_ML + off) = make_uint2(l0, l1);
                c0 += a.x; c1 += a.y; c2 += a.z; c3 += a.w;
            }
            atomicAdd(&sSum[e4c + 0], c0);
            atomicAdd(&sSum[e4c + 1], c1);
            atomicAdd(&sSum[e4c + 2], c2);
            atomicAdd(&sSum[e4c + 3], c3);
        }
        // ---- load v^T tile [128 x 64] hi/lo ----
        for (int i = tid; i < E_DIM * 8; i += NTHREADS) {   // 16B chunks
            int e = i >> 3, c = i & 7;
            int4 vh = *(const int4*)((const char*)(g_vT_hi + (size_t)e * 1024 + tile * TT) + c * 16);
            int4 vl = *(const int4*)((const char*)(g_vT_lo + (size_t)e * 1024 + tile * TT) + c * 16);
            uint32_t off = (uint32_t)(e * SV_STR * 2 + c * 16);
            *(int4*)(base + OFF_VH + off) = vh;
            *(int4*)(base + OFF_VL + off) = vl;
        }
        // ---- load bias tile [64 x 128] fp32 ----
        {
            const float4* b4 = (const float4*)(gb + (size_t)tile * TT * E_DIM);
            float4* d4 = (float4*)sB;
            #pragma unroll
            for (int i = tid; i < TT * E_DIM / 4; i += NTHREADS) d4[i] = b4[i];
        }
        __syncthreads();

        // ---- GEMM1: u[64,128] = m @ W, 3-term split, warps 4(t) x 2(f) ----
        const int tb = wid & 3;           // t block (16 rows)
        const int fh = wid >> 2;          // f half (64 cols)
        float acc[8][4];
        #pragma unroll
        for (int q = 0; q < 8; ++q)
            #pragma unroll
            for (int j = 0; j < 4; ++j) acc[q][j] = 0.0f;

        #pragma unroll
        for (int k0 = 0; k0 < 128; k0 += 16) {
            uint32_t ah[4], al[4];
            uint32_t ao = (uint32_t)((tb * 16 + lrow) * SM_STR + k0 + lcol) * 2u;
            ldsm_x4(ah, sb + OFF_MH + ao);
            ldsm_x4(al, sb + OFF_ML + ao);
            const int brow = k0 + lrow;
            #pragma unroll
            for (int p = 0; p < 4; ++p) {
                int n0 = fh * 64 + p * 16;
                uint32_t bo = (uint32_t)(brow * SW_STR + n0 + lcol) * 2u;
                uint32_t bh[4], bl[4];
                ldsm_x4t(bh, sb + OFF_WH + bo);
                ldsm_x4t(bl, sb + OFF_WL + bo);
                mma16816(acc[2 * p],     ah, bh);
                mma16816(acc[2 * p],     ah, bl);
                mma16816(acc[2 * p],     al, bh);
                mma16816(acc[2 * p + 1], ah, bh + 2);
                mma16816(acc[2 * p + 1], ah, bl + 2);
                mma16816(acc[2 * p + 1], al, bh + 2);
            }
        }

        // ---- epilogue: u = tanh(acc + bias), split -> sU hi/lo ----
        {
            const int r0 = tb * 16 + (lane >> 2);   // local t row
            #pragma unroll
            for (int q = 0; q < 8; ++q) {
                int col = fh * 64 + q * 8 + (lane & 3) * 2;
                float2 bz0 = *(const float2*)(sB + r0 * E_DIM + col);
                float2 bz1 = *(const float2*)(sB + (r0 + 8) * E_DIM + col);
                float u0 = tanh_fast(acc[q][0] + bz0.x);
                float u1 = tanh_fast(acc[q][1] + bz0.y);
                float u2 = tanh_fast(acc[q][2] + bz1.x);
                float u3 = tanh_fast(acc[q][3] + bz1.y);
                uint32_t h0, l0, h1, l1;
                split2(u0, u1, h0, l0);
                split2(u2, u3, h1, l1);
                uint32_t o0 = (uint32_t)(r0 * SU_STR + col) * 2u;
                uint32_t o1 = (uint32_t)((r0 + 8) * SU_STR + col) * 2u;
                *(uint32_t*)(base + OFF_UH + o0) = h0;
                *(uint32_t*)(base + OFF_UL + o0) = l0;
                *(uint32_t*)(base + OFF_UH + o1) = h1;
                *(uint32_t*)(base + OFF_UL + o1) = l1;
            }
        }
        __syncthreads();

        // ---- GEMM2: P[128,128] += vT @ u, 3-term split, warp = 16 e-rows ----
        #pragma unroll
        for (int k0 = 0; k0 < 64; k0 += 16) {
            uint32_t ah[4], al[4];
            uint32_t ao = (uint32_t)((wid * 16 + lrow) * SV_STR + k0 + lcol) * 2u;
            ldsm_x4(ah, sb + OFF_VH + ao);
            ldsm_x4(al, sb + OFF_VL + ao);
            const int brow = k0 + lrow;
            #pragma unroll
            for (int p = 0; p < 8; ++p) {
                uint32_t bo = (uint32_t)(brow * SU_STR + p * 16 + lcol) * 2u;
                uint32_t bh[4], bl[4];
                ldsm_x4t(bh, sb + OFF_UH + bo);
                ldsm_x4t(bl, sb + OFF_UL + bo);
                mma16816(P[2 * p],     ah, bh);
                mma16816(P[2 * p],     ah, bl);
                mma16816(P[2 * p],     al, bh);
                mma16816(P[2 * p + 1], ah, bh + 2);
                mma16816(P[2 * p + 1], ah, bl + 2);
                mma16816(P[2 * p + 1], al, bh + 2);
            }
        }
        __syncthreads();   // protect sM/sV/sU/sB before next tile
    }

    // ---- softmax rows of P + colsum weighting -> sP ----
    float* sP = (float*)base;   // reuse W/M region (64 KB needed, 104 KB available)
    {
        const int r0 = wid * 16 + (lane >> 2);   // global e row
        float mx0 = -3.4e38f, mx1 = -3.4e38f;
        #pragma unroll
        for (int q = 0; q < 16; ++q) {
            mx0 = fmaxf(mx0, fmaxf(P[q][0], P[q][1]));
            mx1 = fmaxf(mx1, fmaxf(P[q][2], P[q][3]));
        }
        mx0 = fmaxf(mx0, __shfl_xor_sync(0xffffffffu, mx0, 1));
        mx0 = fmaxf(mx0, __shfl_xor_sync(0xffffffffu, mx0, 2));
        mx1 = fmaxf(mx1, __shfl_xor_sync(0xffffffffu, mx1, 1));
        mx1 = fmaxf(mx1, __shfl_xor_sync(0xffffffffu, mx1, 2));
        float s0 = 0.0f, s1 = 0.0f;
        #pragma unroll
        for (int q = 0; q < 16; ++q) {
            P[q][0] = __expf(P[q][0] - mx0);
            P[q][1] = __expf(P[q][1] - mx0);
            P[q][2] = __expf(P[q][2] - mx1);
            P[q][3] = __expf(P[q][3] - mx1);
            s0 += P[q][0] + P[q][1];
            s1 += P[q][2] + P[q][3];
        }
        s0 += __shfl_xor_sync(0xffffffffu, s0, 1);
        s0 += __shfl_xor_sync(0xffffffffu, s0, 2);
        s1 += __shfl_xor_sync(0xffffffffu, s1, 1);
        s1 += __shfl_xor_sync(0xffffffffu, s1, 2);
        float w0 = sSum[r0] / s0;
        float w1 = sSum[r0 + 8] / s1;
        #pragma unroll
        for (int q = 0; q < 16; ++q) {
            int col = q * 8 + (lane & 3) * 2;
            *(float2*)(sP + r0 * E_DIM + col)       = make_float2(P[q][0] * w0, P[q][1] * w0);
            *(float2*)(sP + (r0 + 8) * E_DIM + col) = make_float2(P[q][2] * w1, P[q][3] * w1);
        }
    }
    __syncthreads();

    if (tid < E_DIM) {
        float o = 0.0f;
        #pragma unroll 8
        for (int e = 0; e < E_DIM; ++e) o += sP[e * E_DIM + tid];
        gout[(size_t)b * E_DIM + tid] = o;
    }
}

extern "C" void kernel_launch(void* const* d_in, const int* in_sizes, int n_in,
                              void* d_out, int out_size)
{
    const float* m  = (const float*)d_in[0];   // (B, T, E)
    const float* v  = (const float*)d_in[1];   // (T, E)   time-indexed
    const float* W  = (const float*)d_in[2];   // (B, E, E)
    const float* bb = (const float*)d_in[3];   // (T, E)   bias, time-indexed
    float* out = (float*)d_out;                // (B, E)

    const int BE = in_sizes[1];
    const int Bn = BE / E_DIM;                 // 1024

    vsplit_kernel<<<(1024 * E_DIM) / NTHREADS, NTHREADS>>>(v);

    cudaFuncSetAttribute(attn_mv_mma, cudaFuncAttributeMaxDynamicSharedMemorySize, SMEM_REQ);
    attn_mv_mma<<<Bn, NTHREADS, SMEM_REQ>>>(m, W, bb, out);
}

// round 14
// speedup vs baseline: 2.6052x; 1.3637x over previous
#include <cuda_runtime.h>
#include <cuda_bf16.h>
#include <stdint.h>

#define E_DIM 128
#define TT 64
#define NTHREADS 512
#define NTILES 16
// smem strides in bf16 elements
#define SW_STR 136
#define SM_STR 136
#define SU_STR 136
#define SV_STR 72

// byte offsets from 1024-aligned smem base
#define OFF_WH 0u
#define OFF_WL 34816u
#define OFF_MH 69632u
#define OFF_ML 87040u
#define OFF_V0 104448u          /* VH(buf) = OFF_V0 + buf*36864, VL = +18432 */
#define OFF_UH 178176u
#define OFF_UL 195584u
#define OFF_SUM 212992u
#define OFF_RED 213504u
#define SMEM_REQ (215552 + 1024)

// v^T split, shared by all batches: [E rows][1024 t cols]
__device__ __nv_bfloat16 g_vT_hi[E_DIM * 1024];
__device__ __nv_bfloat16 g_vT_lo[E_DIM * 1024];

__device__ __forceinline__ uint32_t s2u(const void* p) {
    uint32_t a;
    asm("{ .reg .u64 t; cvta.to.shared.u64 t, %1; cvt.u32.u64 %0, t; }" : "=r"(a) : "l"(p));
    return a;
}
__device__ __forceinline__ void ldsm_x4(uint32_t* r, uint32_t a) {
    asm volatile("ldmatrix.sync.aligned.m8n8.x4.shared.b16 {%0,%1,%2,%3}, [%4];"
                 : "=r"(r[0]), "=r"(r[1]), "=r"(r[2]), "=r"(r[3]) : "r"(a));
}
__device__ __forceinline__ void ldsm_x4t(uint32_t* r, uint32_t a) {
    asm volatile("ldmatrix.sync.aligned.m8n8.x4.trans.shared.b16 {%0,%1,%2,%3}, [%4];"
                 : "=r"(r[0]), "=r"(r[1]), "=r"(r[2]), "=r"(r[3]) : "r"(a));
}
__device__ __forceinline__ void mma16816(float* c, const uint32_t* a, const uint32_t* b) {
    asm volatile("mma.sync.aligned.m16n8k16.row.col.f32.bf16.bf16.f32 "
                 "{%0,%1,%2,%3}, {%4,%5,%6,%7}, {%8,%9}, {%0,%1,%2,%3};"
                 : "+f"(c[0]), "+f"(c[1]), "+f"(c[2]), "+f"(c[3])
                 : "r"(a[0]), "r"(a[1]), "r"(a[2]), "r"(a[3]), "r"(b[0]), "r"(b[1]));
}
__device__ __forceinline__ uint32_t pkbf2(__nv_bfloat16 a, __nv_bfloat16 b) {
    __nv_bfloat162 t = __halves2bfloat162(a, b);
    return *(uint32_t*)&t;
}
__device__ __forceinline__ void split2(float x0, float x1, uint32_t& hi, uint32_t& lo) {
    __nv_bfloat16 h0 = __float2bfloat16(x0);
    __nv_bfloat16 h1 = __float2bfloat16(x1);
    hi = pkbf2(h0, h1);
    lo = pkbf2(__float2bfloat16(x0 - __bfloat162float(h0)),
               __float2bfloat16(x1 - __bfloat162float(h1)));
}
__device__ __forceinline__ float tanh_fast(float x) {
    float ex = __expf(2.0f * x);
    return 1.0f - __fdividef(2.0f, ex + 1.0f);
}

// ---------------- precompute: split v^T ----------------
__global__ void vsplit_kernel(const float* __restrict__ gv) {
    int w = blockIdx.x * blockDim.x + threadIdx.x;   // 0 .. 131071
    int e = w >> 10, t = w & 1023;
    float x = gv[t * E_DIM + e];
    __nv_bfloat16 h = __float2bfloat16(x);
    g_vT_hi[w] = h;
    g_vT_lo[w] = __float2bfloat16(x - __bfloat162float(h));
}

// ---------------- main kernel ----------------
__global__ void __launch_bounds__(NTHREADS, 1)
attn_mv_mma(const float* __restrict__ gm, const float* __restrict__ gW,
            const float* __restrict__ gb, float* __restrict__ gout)
{
    extern __shared__ char raw[];
    char* base = (char*)(((uintptr_t)raw + 1023) & ~(uintptr_t)1023);
    const uint32_t sb = s2u(base);
    float*  sSum = (float*)(base + OFF_SUM);
    float2* sRed = (float2*)(base + OFF_RED);

    const int b    = blockIdx.x;
    const int tid  = threadIdx.x;
    const int lane = tid & 31;
    const int wid  = tid >> 5;

    const float* mb = gm + (size_t)b * 1024 * E_DIM;

    // ---- stage W split into smem [e rows][f cols], hi/lo ----
    {
        const float4* W4 = (const float4*)(gW + (size_t)b * E_DIM * E_DIM);
        #pragma unroll
        for (int i = tid; i < E_DIM * 32; i += NTHREADS) {
            int e  = i >> 5;
            int f4 = (i & 31) * 4;
            float4 w = W4[i];
            uint32_t h0, l0, h1, l1;
            split2(w.x, w.y, h0, l0);
            split2(w.z, w.w, h1, l1);
            uint32_t off = (uint32_t)(e * SW_STR + f4) * 2u;
            *(uint2*)(base + OFF_WH + off) = make_uint2(h0, h1);
            *(uint2*)(base + OFF_WL + off) = make_uint2(l0, l1);
        }
    }
    if (tid < E_DIM) sSum[tid] = 0.0f;
    __syncthreads();

    const int lrow = lane & 15;
    const int lcol = (lane >> 4) * 8;
    const int e4c  = (tid & 31) * 4;

    // GEMM1 warp tiling: 4(t) x 4(f); GEMM2: 8(e) x 2(f)
    const int tb = wid & 3;
    const int fq = wid >> 2;
    const int ew = wid & 7;
    const int fh = wid >> 3;

    // P accumulators: warp owns e-rows [ew*16, ew*16+16) x f-cols [fh*64, fh*64+64)
    float P[8][4];
    #pragma unroll
    for (int q = 0; q < 8; ++q)
        #pragma unroll
        for (int j = 0; j < 4; ++j) P[q][j] = 0.0f;

    // tile-load staging registers
    float4 mreg[4];
    uint4  vhreg[2], vlreg[2];

    auto ldg_tile = [&](int tile) {
        const float4* m4 = (const float4*)(mb + (size_t)tile * TT * E_DIM);
        #pragma unroll
        for (int k = 0; k < 4; ++k) mreg[k] = m4[tid + k * NTHREADS];
        #pragma unroll
        for (int k = 0; k < 2; ++k) {
            int i = tid + k * NTHREADS;
            int e = i >> 3, c = i & 7;
            vhreg[k] = *(const uint4*)((const char*)(g_vT_hi + (size_t)e * 1024 + tile * TT) + c * 16);
            vlreg[k] = *(const uint4*)((const char*)(g_vT_lo + (size_t)e * 1024 + tile * TT) + c * 16);
        }
    };
    auto sts_tile = [&](int buf) {
        float c0 = 0.f, c1 = 0.f, c2 = 0.f, c3 = 0.f;
        #pragma unroll
        for (int k = 0; k < 4; ++k) {
            int i  = tid + k * NTHREADS;
            int t  = i >> 5;
            int e4 = (i & 31) * 4;
            float4 a = mreg[k];
            uint32_t h0, l0, h1, l1;
            split2(a.x, a.y, h0, l0);
            split2(a.z, a.w, h1, l1);
            uint32_t off = (uint32_t)(t * SM_STR + e4) * 2u;
            *(uint2*)(base + OFF_MH + off) = make_uint2(h0, h1);
            *(uint2*)(base + OFF_ML + off) = make_uint2(l0, l1);
            c0 += a.x; c1 += a.y; c2 += a.z; c3 += a.w;
        }
        atomicAdd(&sSum[e4c + 0], c0);
        atomicAdd(&sSum[e4c + 1], c1);
        atomicAdd(&sSum[e4c + 2], c2);
        atomicAdd(&sSum[e4c + 3], c3);
        uint32_t vb = OFF_V0 + (uint32_t)buf * 36864u;
        #pragma unroll
        for (int k = 0; k < 2; ++k) {
            int i = tid + k * NTHREADS;
            int e = i >> 3, c = i & 7;
            uint32_t off = (uint32_t)(e * SV_STR * 2 + c * 16);
            *(uint4*)(base + vb + off)          = vhreg[k];
            *(uint4*)(base + vb + 18432u + off) = vlreg[k];
        }
    };

    // prologue: tile 0
    ldg_tile(0);
    sts_tile(0);
    int buf = 0;

    for (int tile = 0; tile < NTILES; ++tile) {
        __syncthreads();   // sM, sV[buf] visible; sU free

        // ---- bias prefetch (L2-resident, time-indexed) ----
        const int r0g1 = tb * 16 + (lane >> 2);
        float2 bz[8];
        {
            const float* bp = gb + (size_t)(tile * TT + r0g1) * E_DIM;
            #pragma unroll
            for (int p = 0; p < 2; ++p)
                #pragma unroll
                for (int j = 0; j < 2; ++j) {
                    int col = fq * 32 + p * 16 + j * 8 + (lane & 3) * 2;
                    bz[(2 * p + j) * 2 + 0] = *(const float2*)(bp + col);
                    bz[(2 * p + j) * 2 + 1] = *(const float2*)(bp + 8 * E_DIM + col);
                }
        }

        // ---- GEMM1: u[64,128] = m @ W, 3-term split ----
        float acc[4][4];
        #pragma unroll
        for (int q = 0; q < 4; ++q)
            #pragma unroll
            for (int j = 0; j < 4; ++j) acc[q][j] = 0.0f;

        #pragma unroll
        for (int k0 = 0; k0 < 128; k0 += 16) {
            uint32_t ah[4], al[4];
            uint32_t ao = (uint32_t)((tb * 16 + lrow) * SM_STR + k0 + lcol) * 2u;
            ldsm_x4(ah, sb + OFF_MH + ao);
            ldsm_x4(al, sb + OFF_ML + ao);
            const int brow = k0 + lrow;
            #pragma unroll
            for (int p = 0; p < 2; ++p) {
                int n0 = fq * 32 + p * 16;
                uint32_t bo = (uint32_t)(brow * SW_STR + n0 + lcol) * 2u;
                uint32_t bh[4], bl[4];
                ldsm_x4t(bh, sb + OFF_WH + bo);
                ldsm_x4t(bl, sb + OFF_WL + bo);
                mma16816(acc[2 * p],     ah, bh);
                mma16816(acc[2 * p],     ah, bl);
                mma16816(acc[2 * p],     al, bh);
                mma16816(acc[2 * p + 1], ah, bh + 2);
                mma16816(acc[2 * p + 1], ah, bl + 2);
                mma16816(acc[2 * p + 1], al, bh + 2);
            }
        }

        // ---- epilogue: u = tanh(acc + bias), split -> sU hi/lo ----
        #pragma unroll
        for (int p = 0; p < 2; ++p)
            #pragma unroll
            for (int j = 0; j < 2; ++j) {
                int q = 2 * p + j;
                int col = fq * 32 + p * 16 + j * 8 + (lane & 3) * 2;
                float u0 = tanh_fast(acc[q][0] + bz[2 * q].x);
                float u1 = tanh_fast(acc[q][1] + bz[2 * q].y);
                float u2 = tanh_fast(acc[q][2] + bz[2 * q + 1].x);
                float u3 = tanh_fast(acc[q][3] + bz[2 * q + 1].y);
                uint32_t h0, l0, h1, l1;
                split2(u0, u1, h0, l0);
                split2(u2, u3, h1, l1);
                uint32_t o0 = (uint32_t)(r0g1 * SU_STR + col) * 2u;
                uint32_t o1 = (uint32_t)((r0g1 + 8) * SU_STR + col) * 2u;
                *(uint32_t*)(base + OFF_UH + o0) = h0;
                *(uint32_t*)(base + OFF_UL + o0) = l0;
                *(uint32_t*)(base + OFF_UH + o1) = h1;
                *(uint32_t*)(base + OFF_UL + o1) = l1;
            }
        __syncthreads();   // sU ready; all GEMM1 reads of sM done

        // ---- prefetch next tile (LDG latency hides under GEMM2) ----
        const bool pf = (tile + 1 < NTILES);
        if (pf) ldg_tile(tile + 1);

        // ---- GEMM2: P += vT @ u, 3-term split ----
        const uint32_t vbh = OFF_V0 + (uint32_t)buf * 36864u;
        #pragma unroll
        for (int k0 = 0; k0 < 64; k0 += 16) {
            uint32_t ah[4], al[4];
            uint32_t ao = (uint32_t)((ew * 16 + lrow) * SV_STR + k0 + lcol) * 2u;
            ldsm_x4(ah, sb + vbh + ao);
            ldsm_x4(al, sb + vbh + 18432u + ao);
            const int brow = k0 + lrow;
            #pragma unroll
            for (int p = 0; p < 4; ++p) {
                uint32_t bo = (uint32_t)(brow * SU_STR + fh * 64 + p * 16 + lcol) * 2u;
                uint32_t bh[4], bl[4];
                ldsm_x4t(bh, sb + OFF_UH + bo);
                ldsm_x4t(bl, sb + OFF_UL + bo);
                mma16816(P[2 * p],     ah, bh);
                mma16816(P[2 * p],     ah, bl);
                mma16816(P[2 * p],     al, bh);
                mma16816(P[2 * p + 1], ah, bh + 2);
                mma16816(P[2 * p + 1], ah, bl + 2);
                mma16816(P[2 * p + 1], al, bh + 2);
            }
        }

        if (pf) sts_tile(buf ^ 1);
        buf ^= 1;
    }

    // ---- softmax rows of P (split across 2 f-half warps) + weighting ----
    float* sP = (float*)base;   // reuse W/M region
    {
        const int r0 = ew * 16 + (lane >> 2);
        float mx0 = -3.4e38f, mx1 = -3.4e38f;
        #pragma unroll
        for (int q = 0; q < 8; ++q) {
            mx0 = fmaxf(mx0, fmaxf(P[q][0], P[q][1]));
            mx1 = fmaxf(mx1, fmaxf(P[q][2], P[q][3]));
        }
        mx0 = fmaxf(mx0, __shfl_xor_sync(0xffffffffu, mx0, 1));
        mx0 = fmaxf(mx0, __shfl_xor_sync(0xffffffffu, mx0, 2));
        mx1 = fmaxf(mx1, __shfl_xor_sync(0xffffffffu, mx1, 1));
        mx1 = fmaxf(mx1, __shfl_xor_sync(0xffffffffu, mx1, 2));
        float s0 = 0.0f, s1 = 0.0f;
        #pragma unroll
        for (int q = 0; q < 8; ++q) {
            P[q][0] = __expf(P[q][0] - mx0);
            P[q][1] = __expf(P[q][1] - mx0);
            P[q][2] = __expf(P[q][2] - mx1);
            P[q][3] = __expf(P[q][3] - mx1);
            s0 += P[q][0] + P[q][1];
            s1 += P[q][2] + P[q][3];
        }
        s0 += __shfl_xor_sync(0xffffffffu, s0, 1);
        s0 += __shfl_xor_sync(0xffffffffu, s0, 2);
        s1 += __shfl_xor_sync(0xffffffffu, s1, 1);
        s1 += __shfl_xor_sync(0xffffffffu, s1, 2);
        if ((lane & 3) == 0) {
            sRed[r0 * 2 + fh]       = make_float2(mx0, s0);
            sRed[(r0 + 8) * 2 + fh] = make_float2(mx1, s1);
        }
        __syncthreads();
        float2 A0 = sRed[r0 * 2 + 0],       A1 = sRed[r0 * 2 + 1];
        float2 B0 = sRed[(r0 + 8) * 2 + 0], B1 = sRed[(r0 + 8) * 2 + 1];
        float M0 = fmaxf(A0.x, A1.x);
        float S0 = A0.y * __expf(A0.x - M0) + A1.y * __expf(A1.x - M0);
        float M1 = fmaxf(B0.x, B1.x);
        float S1 = B0.y * __expf(B0.x - M1) + B1.y * __expf(B1.x - M1);
        float sc0 = __expf(mx0 - M0) * sSum[r0] / S0;
        float sc1 = __expf(mx1 - M1) * sSum[r0 + 8] / S1;
        #pragma unroll
        for (int p = 0; p < 4; ++p)
            #pragma unroll
            for (int j = 0; j < 2; ++j) {
                int q = 2 * p + j;
                int col = fh * 64 + p * 16 + j * 8 + (lane & 3) * 2;
                *(float2*)(sP + r0 * E_DIM + col)       = make_float2(P[q][0] * sc0, P[q][1] * sc0);
                *(float2*)(sP + (r0 + 8) * E_DIM + col) = make_float2(P[q][2] * sc1, P[q][3] * sc1);
            }
    }
    __syncthreads();

    if (tid < E_DIM) {
        float o = 0.0f;
        #pragma unroll 8
        for (int e = 0; e < E_DIM; ++e) o += sP[e * E_DIM + tid];
        gout[(size_t)b * E_DIM + tid] = o;
    }
}

extern "C" void kernel_launch(void* const* d_in, const int* in_sizes, int n_in,
                              void* d_out, int out_size)
{
    const float* m  = (const float*)d_in[0];   // (B, T, E)
    const float* v  = (const float*)d_in[1];   // (T, E)   time-indexed
    const float* W  = (const float*)d_in[2];   // (B, E, E)
    const float* bb = (const float*)d_in[3];   // (T, E)   bias, time-indexed
    float* out = (float*)d_out;                // (B, E)

    const int BE = in_sizes[1];
    const int Bn = BE / E_DIM;                 // 1024

    vsplit_kernel<<<(1024 * E_DIM) / 256, 256>>>(v);

    cudaFuncSetAttribute(attn_mv_mma, cudaFuncAttributeMaxDynamicSharedMemorySize, SMEM_REQ);
    attn_mv_mma<<<Bn, NTHREADS, SMEM_REQ>>>(m, W, bb, out);
}